// round 14
// baseline (speedup 1.0000x reference)
#include <cuda_runtime.h>
#include <cuda_fp16.h>
#include <cstdint>

#define NN 50000
#define EE 800000

// ---------------- scratch (device globals: no allocation allowed) ----------
__device__ float g_q[NN * 64];
__device__ __align__(8) uint2 g_kvh[NN * 32];  // [node][lane] = {k half2, v half2}
__device__ float g_h[NN * 64];    // layer1 skip, then layer1 output (post-relu)
__device__ float g_s2[NN * 64];   // layer2 skip
__device__ int g_deg[NN];
__device__ int g_off[NN + 1];
__device__ int g_cur[NN];
__device__ int g_srcs[EE];
// W in HMMA fp16 fragment layout: [mat][kt][nt][lane] -> uint2 (b0,b1)
__device__ __align__(16) uint2 g_w1[4 * 8 * 8 * 32];
__device__ __align__(16) uint2 g_w2[4 * 4 * 8 * 32];

struct G4w {
    const float* W[4];
    const float* b[4];
};

// ---------------- mma.sync m16n8k16 fp16 (sm_80+, portable PTX) -------------
__device__ __forceinline__ void mma_f16(float* c, const uint32_t* a, const uint32_t* b) {
    asm("mma.sync.aligned.m16n8k16.row.col.f32.f16.f16.f32 "
        "{%0,%1,%2,%3}, {%4,%5,%6,%7}, {%8,%9}, {%0,%1,%2,%3};\n"
        : "+f"(c[0]), "+f"(c[1]), "+f"(c[2]), "+f"(c[3])
        : "r"(a[0]), "r"(a[1]), "r"(a[2]), "r"(a[3]), "r"(b[0]), "r"(b[1]));
}

__device__ __forceinline__ uint32_t pack_f16x2(float x, float y) {
    __half2 h = __float22half2_rn(make_float2(x, y));
    return *reinterpret_cast<uint32_t*>(&h);
}

__device__ __forceinline__ float2 h22f2(uint32_t u) {
    return __half22float2(*reinterpret_cast<__half2*>(&u));
}

// ---------------- W -> fp16 HMMA-fragment conversion (main stream) -----------
__global__ void wprep_kernel(G4w w1, G4w w2) {
    int idx = blockIdx.x * blockDim.x + threadIdx.x;
    const int L1N = 4 * 8 * 8 * 32;   // 8192
    const int L2N = 4 * 4 * 8 * 32;   // 4096
    if (idx >= L1N + L2N) return;
    const float* W;
    uint2* dst;
    int C, KT, rem;
    if (idx < L1N) {
        C = 128; KT = 8;
        int mat = idx / (8 * 8 * 32);
        rem = idx - mat * (8 * 8 * 32);
        W = w1.W[mat];
        dst = g_w1 + (size_t)mat * KT * 8 * 32;
    } else {
        C = 64; KT = 4;
        int j = idx - L1N;
        int mat = j / (4 * 8 * 32);
        rem = j - mat * (4 * 8 * 32);
        W = w2.W[mat];
        dst = g_w2 + (size_t)mat * KT * 8 * 32;
    }
    int kt = rem / (8 * 32);
    int r2 = rem - kt * (8 * 32);
    int nt = r2 >> 5;
    int lane = r2 & 31;
    int k0 = kt * 16 + (lane & 3) * 2;
    int n = nt * 8 + (lane >> 2);

    float a0 = W[n * C + k0],     a1 = W[n * C + k0 + 1];
    float a2 = W[n * C + k0 + 8], a3 = W[n * C + k0 + 9];

    int fo = (kt * 8 + nt) * 32 + lane;
    dst[fo] = make_uint2(pack_f16x2(a0, a1), pack_f16x2(a2, a3));
}

// ---------------- CSR build (side stream) ------------------------------------
__global__ void hist_kernel(const int* __restrict__ ei) {
    int e = blockIdx.x * blockDim.x + threadIdx.x;
    if (e < EE) atomicAdd(&g_deg[__ldg(ei + EE + e)], 1);
}

__global__ void scan_kernel() {
    __shared__ int sh[1024];
    const int tid = threadIdx.x;
    const int CHUNK = (NN + 1023) / 1024;
    const int s0 = tid * CHUNK;
    int sum = 0;
    #pragma unroll 4
    for (int i = 0; i < CHUNK; i++) {
        int idx = s0 + i;
        if (idx < NN) sum += g_deg[idx];
    }
    sh[tid] = sum;
    __syncthreads();
    int val = sum;
    for (int off = 1; off < 1024; off <<= 1) {
        int t = (tid >= off) ? sh[tid - off] : 0;
        __syncthreads();
        val += t;
        sh[tid] = val;
        __syncthreads();
    }
    int run = val - sum;
    for (int i = 0; i < CHUNK; i++) {
        int idx = s0 + i;
        if (idx < NN) {
            g_off[idx] = run;
            g_cur[idx] = run;
            run += g_deg[idx];
        }
    }
    if (tid == 0) g_off[NN] = EE;
}

__global__ void scatter_kernel(const int* __restrict__ ei) {
    int e = blockIdx.x * blockDim.x + threadIdx.x;
    if (e < EE) {
        int d = __ldg(ei + EE + e);
        int p = atomicAdd(&g_cur[d], 1);
        g_srcs[p] = __ldg(ei + e);
    }
}

// ---------------- single-pass fp16 HMMA fused QKVS GEMM ----------------------
template <int C, int LAYER>
__global__ __launch_bounds__(256, 2) void gemm_mma_kernel(const float* __restrict__ Xin,
                                                          G4w a, float qscale) {
    constexpr int KT = C / 16;
    extern __shared__ uint32_t sA[];          // [KT][4 mt][32 lane][4 regs] fp16x2

    const float* X = (LAYER == 1) ? Xin : g_h;
    const int tid = threadIdx.x;
    const int row0 = blockIdx.x * 64;

    constexpr int PAIRS = C / 2;
    for (int p = tid; p < 64 * PAIRS; p += 256) {
        int r = p / PAIRS;
        int kp = p - r * PAIRS;
        int rg = row0 + r;
        float2 xv = make_float2(0.f, 0.f);
        if (rg < NN) xv = *reinterpret_cast<const float2*>(X + (size_t)rg * C + kp * 2);
        int m = r & 15, mt = r >> 4;
        int k = kp * 2, kt = k >> 4, kk = k & 15;
        int lane = (m & 7) * 4 + ((kk & 7) >> 1);
        int reg = ((m >> 3) & 1) | ((kk >> 3) << 1);
        sA[((kt * 4 + mt) * 32 + lane) * 4 + reg] = pack_f16x2(xv.x, xv.y);
    }
    __syncthreads();

    const int w = tid >> 5;
    const int lane = tid & 31;
    const int mat = w >> 1;
    const int rowhalf = w & 1;
    const uint2* B = ((LAYER == 1) ? g_w1 : g_w2) + (size_t)mat * KT * 8 * 32;

    float acc[2][8][4];
    #pragma unroll
    for (int i = 0; i < 2; i++)
        #pragma unroll
        for (int j = 0; j < 8; j++)
            #pragma unroll
            for (int q = 0; q < 4; q++) acc[i][j][q] = 0.f;

    #pragma unroll
    for (int kt = 0; kt < KT; kt++) {
        uint4 Af[2];
        #pragma unroll
        for (int mt2 = 0; mt2 < 2; mt2++) {
            int mt = rowhalf * 2 + mt2;
            Af[mt2] = *reinterpret_cast<const uint4*>(sA + ((kt * 4 + mt) * 32 + lane) * 4);
        }
        uint2 b[8];
        #pragma unroll
        for (int nt = 0; nt < 8; nt++) b[nt] = __ldg(B + (kt * 8 + nt) * 32 + lane);
        #pragma unroll
        for (int nt = 0; nt < 8; nt++)
            #pragma unroll
            for (int mt2 = 0; mt2 < 2; mt2++)
                mma_f16(acc[mt2][nt], reinterpret_cast<uint32_t*>(&Af[mt2]),
                        reinterpret_cast<uint32_t*>(&b[nt]));
    }

    // ---- epilogue: bias + scale; q/skip fp32, k/v packed half2 -> g_kvh ----
    const float sc = (mat == 0) ? qscale : 1.0f;
    const float* bias = a.b[mat];
    uint32_t* kvw = reinterpret_cast<uint32_t*>(g_kvh);
    float* Of = (mat == 0) ? g_q : ((LAYER == 1) ? g_h : g_s2);
    #pragma unroll
    for (int nt = 0; nt < 8; nt++) {
        int col = nt * 8 + (lane & 3) * 2;
        float b0 = __ldg(bias + col);
        float b1 = __ldg(bias + col + 1);
        #pragma unroll
        for (int mt2 = 0; mt2 < 2; mt2++) {
            int r = row0 + (rowhalf * 2 + mt2) * 16 + (lane >> 2);
            #pragma unroll
            for (int half = 0; half < 2; half++) {
                int rr = r + half * 8;
                if (rr >= NN) continue;
                float o0 = (acc[mt2][nt][half * 2 + 0] + b0) * sc;
                float o1 = (acc[mt2][nt][half * 2 + 1] + b1) * sc;
                if (mat == 1 || mat == 2) {
                    kvw[((size_t)rr * 32 + (col >> 1)) * 2 + (mat - 1)] =
                        pack_f16x2(o0, o1);
                } else {
                    *reinterpret_cast<float2*>(Of + (size_t)rr * 64 + col) =
                        make_float2(o0, o1);
                }
            }
        }
    }
}

// ---------------- per-destination-node attention (warp per node) ------------
// No max-subtraction (logits are O(1): 0.05-scale weights; fp32 exp safe).
// Unroll x8: all 8 idx loads + 8 kv gathers issued before any compute -> 8
// independent L2 requests in flight per stall window.
template <int H, bool RELU, bool L1>
__global__ void node_attn_kernel(float* __restrict__ out_param) {
    constexpr int GROUP = 32 / H;

    int warp = (blockIdx.x * blockDim.x + threadIdx.x) >> 5;
    if (warp >= NN) return;
    const int lane = threadIdx.x & 31;

    const float* skip = L1 ? g_h : g_s2;
    float* out = L1 ? g_h : out_param;

    const int beg = g_off[warp];
    const int end = g_off[warp + 1];

    float2 qr = *reinterpret_cast<const float2*>(g_q + (size_t)warp * 64 + lane * 2);
    const float qx = qr.x, qy = qr.y;
    float2 sk = *reinterpret_cast<const float2*>(skip + (size_t)warp * 64 + lane * 2);

    float den = 0.f, ax = 0.f, ay = 0.f;

    int i = beg;
    for (; i + 8 <= end; i += 8) {
        int s[8];
        #pragma unroll
        for (int j = 0; j < 8; j++) s[j] = __ldg(&g_srcs[i + j]);
        uint2 c[8];
        #pragma unroll
        for (int j = 0; j < 8; j++) c[j] = __ldg(&g_kvh[(size_t)s[j] * 32 + lane]);

        float p[8];
        #pragma unroll
        for (int j = 0; j < 8; j++) {
            float2 kk = h22f2(c[j].x);
            p[j] = qx * kk.x + qy * kk.y;
        }
        #pragma unroll
        for (int o = 1; o < GROUP; o <<= 1) {
            #pragma unroll
            for (int j = 0; j < 8; j++) p[j] += __shfl_xor_sync(0xffffffffu, p[j], o);
        }
        #pragma unroll
        for (int j = 0; j < 8; j++) {
            float e = __expf(p[j]);
            float2 vv = h22f2(c[j].y);
            den += e;
            ax += e * vv.x;
            ay += e * vv.y;
        }
    }
    for (; i < end; i++) {
        int s = __ldg(&g_srcs[i]);
        uint2 c = __ldg(&g_kvh[(size_t)s * 32 + lane]);
        float2 kk = h22f2(c.x), vv = h22f2(c.y);
        float p = qx * kk.x + qy * kk.y;
        #pragma unroll
        for (int o = 1; o < GROUP; o <<= 1) p += __shfl_xor_sync(0xffffffffu, p, o);
        float e = __expf(p);
        den += e;
        ax += e * vv.x;
        ay += e * vv.y;
    }

    const float rden = (den > 0.f) ? (1.0f / den) : 0.0f;   // deg==0 -> out = skip
    float ox = ax * rden + sk.x;
    float oy = ay * rden + sk.y;
    if (RELU) {
        ox = fmaxf(ox, 0.f);
        oy = fmaxf(oy, 0.f);
    }
    *reinterpret_cast<float2*>(out + (size_t)warp * 64 + lane * 2) = make_float2(ox, oy);
}

// ---------------- launch ------------------------------------------------------
// Fork/join: CSR build (memset->hist->scan->scatter) on a side stream overlaps
// with wprep->gemm1 on the main stream; join before attn1.
extern "C" void kernel_launch(void* const* d_in, const int* in_sizes, int n_in,
                              void* d_out, int out_size) {
    (void)in_sizes; (void)n_in; (void)out_size;
    const float* x = (const float*)d_in[0];
    const int* ei = (const int*)d_in[1];

    static cudaStream_t s_csr = nullptr;
    static cudaEvent_t ev_fork = nullptr, ev_join = nullptr;
    if (s_csr == nullptr) {
        cudaStreamCreateWithFlags(&s_csr, cudaStreamNonBlocking);
        cudaEventCreateWithFlags(&ev_fork, cudaEventDisableTiming);
        cudaEventCreateWithFlags(&ev_join, cudaEventDisableTiming);
        constexpr int SMEM1c = 8 * 4 * 32 * 16;
        constexpr int SMEM2c = 4 * 4 * 32 * 16;
        cudaFuncSetAttribute(gemm_mma_kernel<128, 1>,
                             cudaFuncAttributeMaxDynamicSharedMemorySize, SMEM1c);
        cudaFuncSetAttribute(gemm_mma_kernel<64, 2>,
                             cudaFuncAttributeMaxDynamicSharedMemorySize, SMEM2c);
    }
    constexpr int SMEM1 = 8 * 4 * 32 * 16;   // 16384 bytes (C=128)
    constexpr int SMEM2 = 4 * 4 * 32 * 16;   // 8192 bytes (C=64)

    G4w w1, w2;
    w1.W[0] = (const float*)d_in[2];  w1.b[0] = (const float*)d_in[3];
    w1.W[1] = (const float*)d_in[4];  w1.b[1] = (const float*)d_in[5];
    w1.W[2] = (const float*)d_in[6];  w1.b[2] = (const float*)d_in[7];
    w1.W[3] = (const float*)d_in[8];  w1.b[3] = (const float*)d_in[9];
    w2.W[0] = (const float*)d_in[10]; w2.b[0] = (const float*)d_in[11];
    w2.W[1] = (const float*)d_in[12]; w2.b[1] = (const float*)d_in[13];
    w2.W[2] = (const float*)d_in[14]; w2.b[2] = (const float*)d_in[15];
    w2.W[3] = (const float*)d_in[16]; w2.b[3] = (const float*)d_in[17];

    void* degp = nullptr;
    cudaGetSymbolAddress(&degp, g_deg);

    // ---- fork: CSR chain on side stream ----
    cudaEventRecord(ev_fork, 0);
    cudaStreamWaitEvent(s_csr, ev_fork, 0);
    cudaMemsetAsync(degp, 0, NN * sizeof(int), s_csr);
    hist_kernel<<<(EE + 255) / 256, 256, 0, s_csr>>>(ei);
    scan_kernel<<<1, 1024, 0, s_csr>>>();
    scatter_kernel<<<(EE + 255) / 256, 256, 0, s_csr>>>(ei);
    cudaEventRecord(ev_join, s_csr);

    // ---- main stream: wprep -> gemm1 (independent of CSR) ----
    wprep_kernel<<<48, 256>>>(w1, w2);
    const int NB = (NN + 63) / 64;   // 782
    gemm_mma_kernel<128, 1><<<NB, 256, SMEM1>>>(x, w1, 0.25f);   // qscale 1/4

    // ---- join, then the dependent chain ----
    cudaStreamWaitEvent(0, ev_join, 0);
    node_attn_kernel<4, true, true><<<(NN * 32) / 256, 256>>>(nullptr);
    gemm_mma_kernel<64, 2><<<NB, 256, SMEM2>>>(x, w2, 0.125f);   // qscale 1/8
    node_attn_kernel<1, false, false><<<(NN * 32) / 256, 256>>>((float*)d_out);
}

// round 15
// speedup vs baseline: 1.0258x; 1.0258x over previous
#include <cuda_runtime.h>
#include <cuda_fp16.h>
#include <cstdint>

#define NN 50000
#define EE 800000

// ---------------- scratch (device globals: no allocation allowed) ----------
__device__ float g_q[NN * 64];
__device__ __align__(8) uint2 g_kvh[NN * 32];  // [node][lane] = {k half2, v half2}
__device__ float g_h[NN * 64];    // layer1 skip, then layer1 output (post-relu)
__device__ float g_s2[NN * 64];   // layer2 skip
__device__ int g_deg[NN];
__device__ int g_off[NN + 1];
__device__ int g_cur[NN];
__device__ int g_srcs[EE];
// W in HMMA fp16 fragment layout: [mat][kt][nt][lane] -> uint2 (b0,b1)
__device__ __align__(16) uint2 g_w1[4 * 8 * 8 * 32];
__device__ __align__(16) uint2 g_w2[4 * 4 * 8 * 32];

struct G4w {
    const float* W[4];
    const float* b[4];
};

// ---------------- mma.sync m16n8k16 fp16 (sm_80+, portable PTX) -------------
__device__ __forceinline__ void mma_f16(float* c, const uint32_t* a, const uint32_t* b) {
    asm("mma.sync.aligned.m16n8k16.row.col.f32.f16.f16.f32 "
        "{%0,%1,%2,%3}, {%4,%5,%6,%7}, {%8,%9}, {%0,%1,%2,%3};\n"
        : "+f"(c[0]), "+f"(c[1]), "+f"(c[2]), "+f"(c[3])
        : "r"(a[0]), "r"(a[1]), "r"(a[2]), "r"(a[3]), "r"(b[0]), "r"(b[1]));
}

__device__ __forceinline__ uint32_t pack_f16x2(float x, float y) {
    __half2 h = __float22half2_rn(make_float2(x, y));
    return *reinterpret_cast<uint32_t*>(&h);
}

__device__ __forceinline__ float2 h22f2(uint32_t u) {
    return __half22float2(*reinterpret_cast<__half2*>(&u));
}

// ---------------- W -> fp16 HMMA-fragment conversion (main stream) -----------
__global__ void wprep_kernel(G4w w1, G4w w2) {
    int idx = blockIdx.x * blockDim.x + threadIdx.x;
    const int L1N = 4 * 8 * 8 * 32;   // 8192
    const int L2N = 4 * 4 * 8 * 32;   // 4096
    if (idx >= L1N + L2N) return;
    const float* W;
    uint2* dst;
    int C, KT, rem;
    if (idx < L1N) {
        C = 128; KT = 8;
        int mat = idx / (8 * 8 * 32);
        rem = idx - mat * (8 * 8 * 32);
        W = w1.W[mat];
        dst = g_w1 + (size_t)mat * KT * 8 * 32;
    } else {
        C = 64; KT = 4;
        int j = idx - L1N;
        int mat = j / (4 * 8 * 32);
        rem = j - mat * (4 * 8 * 32);
        W = w2.W[mat];
        dst = g_w2 + (size_t)mat * KT * 8 * 32;
    }
    int kt = rem / (8 * 32);
    int r2 = rem - kt * (8 * 32);
    int nt = r2 >> 5;
    int lane = r2 & 31;
    int k0 = kt * 16 + (lane & 3) * 2;
    int n = nt * 8 + (lane >> 2);

    float a0 = W[n * C + k0],     a1 = W[n * C + k0 + 1];
    float a2 = W[n * C + k0 + 8], a3 = W[n * C + k0 + 9];

    int fo = (kt * 8 + nt) * 32 + lane;
    dst[fo] = make_uint2(pack_f16x2(a0, a1), pack_f16x2(a2, a3));
}

// ---------------- CSR build (side stream) ------------------------------------
__global__ void hist_kernel(const int* __restrict__ ei) {
    int e = blockIdx.x * blockDim.x + threadIdx.x;
    if (e < EE) atomicAdd(&g_deg[__ldg(ei + EE + e)], 1);
}

__global__ void scan_kernel() {
    __shared__ int sh[1024];
    const int tid = threadIdx.x;
    const int CHUNK = (NN + 1023) / 1024;
    const int s0 = tid * CHUNK;
    int sum = 0;
    #pragma unroll 4
    for (int i = 0; i < CHUNK; i++) {
        int idx = s0 + i;
        if (idx < NN) sum += g_deg[idx];
    }
    sh[tid] = sum;
    __syncthreads();
    int val = sum;
    for (int off = 1; off < 1024; off <<= 1) {
        int t = (tid >= off) ? sh[tid - off] : 0;
        __syncthreads();
        val += t;
        sh[tid] = val;
        __syncthreads();
    }
    int run = val - sum;
    for (int i = 0; i < CHUNK; i++) {
        int idx = s0 + i;
        if (idx < NN) {
            g_off[idx] = run;
            g_cur[idx] = run;
            run += g_deg[idx];
        }
    }
    if (tid == 0) g_off[NN] = EE;
}

__global__ void scatter_kernel(const int* __restrict__ ei) {
    int e = blockIdx.x * blockDim.x + threadIdx.x;
    if (e < EE) {
        int d = __ldg(ei + EE + e);
        int p = atomicAdd(&g_cur[d], 1);
        g_srcs[p] = __ldg(ei + e);
    }
}

// ---------------- single-pass fp16 HMMA fused QKVS GEMM ----------------------
template <int C, int LAYER>
__global__ __launch_bounds__(256, 2) void gemm_mma_kernel(const float* __restrict__ Xin,
                                                          G4w a, float qscale) {
    constexpr int KT = C / 16;
    extern __shared__ uint32_t sA[];          // [KT][4 mt][32 lane][4 regs] fp16x2

    const float* X = (LAYER == 1) ? Xin : g_h;
    const int tid = threadIdx.x;
    const int row0 = blockIdx.x * 64;

    constexpr int PAIRS = C / 2;
    for (int p = tid; p < 64 * PAIRS; p += 256) {
        int r = p / PAIRS;
        int kp = p - r * PAIRS;
        int rg = row0 + r;
        float2 xv = make_float2(0.f, 0.f);
        if (rg < NN) xv = *reinterpret_cast<const float2*>(X + (size_t)rg * C + kp * 2);
        int m = r & 15, mt = r >> 4;
        int k = kp * 2, kt = k >> 4, kk = k & 15;
        int lane = (m & 7) * 4 + ((kk & 7) >> 1);
        int reg = ((m >> 3) & 1) | ((kk >> 3) << 1);
        sA[((kt * 4 + mt) * 32 + lane) * 4 + reg] = pack_f16x2(xv.x, xv.y);
    }
    __syncthreads();

    const int w = tid >> 5;
    const int lane = tid & 31;
    const int mat = w >> 1;
    const int rowhalf = w & 1;
    const uint2* B = ((LAYER == 1) ? g_w1 : g_w2) + (size_t)mat * KT * 8 * 32;

    float acc[2][8][4];
    #pragma unroll
    for (int i = 0; i < 2; i++)
        #pragma unroll
        for (int j = 0; j < 8; j++)
            #pragma unroll
            for (int q = 0; q < 4; q++) acc[i][j][q] = 0.f;

    #pragma unroll
    for (int kt = 0; kt < KT; kt++) {
        uint4 Af[2];
        #pragma unroll
        for (int mt2 = 0; mt2 < 2; mt2++) {
            int mt = rowhalf * 2 + mt2;
            Af[mt2] = *reinterpret_cast<const uint4*>(sA + ((kt * 4 + mt) * 32 + lane) * 4);
        }
        uint2 b[8];
        #pragma unroll
        for (int nt = 0; nt < 8; nt++) b[nt] = __ldg(B + (kt * 8 + nt) * 32 + lane);
        #pragma unroll
        for (int nt = 0; nt < 8; nt++)
            #pragma unroll
            for (int mt2 = 0; mt2 < 2; mt2++)
                mma_f16(acc[mt2][nt], reinterpret_cast<uint32_t*>(&Af[mt2]),
                        reinterpret_cast<uint32_t*>(&b[nt]));
    }

    // ---- epilogue: bias + scale; q/skip fp32, k/v packed half2 -> g_kvh ----
    const float sc = (mat == 0) ? qscale : 1.0f;
    const float* bias = a.b[mat];
    uint32_t* kvw = reinterpret_cast<uint32_t*>(g_kvh);
    float* Of = (mat == 0) ? g_q : ((LAYER == 1) ? g_h : g_s2);
    #pragma unroll
    for (int nt = 0; nt < 8; nt++) {
        int col = nt * 8 + (lane & 3) * 2;
        float b0 = __ldg(bias + col);
        float b1 = __ldg(bias + col + 1);
        #pragma unroll
        for (int mt2 = 0; mt2 < 2; mt2++) {
            int r = row0 + (rowhalf * 2 + mt2) * 16 + (lane >> 2);
            #pragma unroll
            for (int half = 0; half < 2; half++) {
                int rr = r + half * 8;
                if (rr >= NN) continue;
                float o0 = (acc[mt2][nt][half * 2 + 0] + b0) * sc;
                float o1 = (acc[mt2][nt][half * 2 + 1] + b1) * sc;
                if (mat == 1 || mat == 2) {
                    kvw[((size_t)rr * 32 + (col >> 1)) * 2 + (mat - 1)] =
                        pack_f16x2(o0, o1);
                } else {
                    *reinterpret_cast<float2*>(Of + (size_t)rr * 64 + col) =
                        make_float2(o0, o1);
                }
            }
        }
    }
}

// ---------------- per-destination-node attention (warp per node) ------------
// No max-subtraction (logits are O(1): 0.05-scale weights; fp32 exp safe).
// 64-thread CTAs (2 warps): straggler granule = 2 nodes instead of 8 — CTA
// slots recycle as soon as both warps finish, cutting Poisson-degree
// imbalance overhead; max occupancy unchanged (32 CTAs x 64 = 2048 thr/SM).
template <int H, bool RELU, bool L1>
__global__ __launch_bounds__(64) void node_attn_kernel(float* __restrict__ out_param) {
    constexpr int GROUP = 32 / H;

    int warp = (blockIdx.x * blockDim.x + threadIdx.x) >> 5;
    if (warp >= NN) return;
    const int lane = threadIdx.x & 31;

    const float* skip = L1 ? g_h : g_s2;
    float* out = L1 ? g_h : out_param;

    const int beg = g_off[warp];
    const int end = g_off[warp + 1];

    float2 qr = *reinterpret_cast<const float2*>(g_q + (size_t)warp * 64 + lane * 2);
    const float qx = qr.x, qy = qr.y;
    float2 sk = *reinterpret_cast<const float2*>(skip + (size_t)warp * 64 + lane * 2);

    float den = 0.f, ax = 0.f, ay = 0.f;

    int i = beg;
    for (; i + 8 <= end; i += 8) {
        int s[8];
        #pragma unroll
        for (int j = 0; j < 8; j++) s[j] = __ldg(&g_srcs[i + j]);
        uint2 c[8];
        #pragma unroll
        for (int j = 0; j < 8; j++) c[j] = __ldg(&g_kvh[(size_t)s[j] * 32 + lane]);

        float p[8];
        #pragma unroll
        for (int j = 0; j < 8; j++) {
            float2 kk = h22f2(c[j].x);
            p[j] = qx * kk.x + qy * kk.y;
        }
        #pragma unroll
        for (int o = 1; o < GROUP; o <<= 1) {
            #pragma unroll
            for (int j = 0; j < 8; j++) p[j] += __shfl_xor_sync(0xffffffffu, p[j], o);
        }
        #pragma unroll
        for (int j = 0; j < 8; j++) {
            float e = __expf(p[j]);
            float2 vv = h22f2(c[j].y);
            den += e;
            ax += e * vv.x;
            ay += e * vv.y;
        }
    }
    for (; i < end; i++) {
        int s = __ldg(&g_srcs[i]);
        uint2 c = __ldg(&g_kvh[(size_t)s * 32 + lane]);
        float2 kk = h22f2(c.x), vv = h22f2(c.y);
        float p = qx * kk.x + qy * kk.y;
        #pragma unroll
        for (int o = 1; o < GROUP; o <<= 1) p += __shfl_xor_sync(0xffffffffu, p, o);
        float e = __expf(p);
        den += e;
        ax += e * vv.x;
        ay += e * vv.y;
    }

    const float rden = (den > 0.f) ? (1.0f / den) : 0.0f;   // deg==0 -> out = skip
    float ox = ax * rden + sk.x;
    float oy = ay * rden + sk.y;
    if (RELU) {
        ox = fmaxf(ox, 0.f);
        oy = fmaxf(oy, 0.f);
    }
    *reinterpret_cast<float2*>(out + (size_t)warp * 64 + lane * 2) = make_float2(ox, oy);
}

// ---------------- launch ------------------------------------------------------
// Fork/join: CSR build (memset->hist->scan->scatter) on a side stream overlaps
// with wprep->gemm1 on the main stream; join before attn1.
extern "C" void kernel_launch(void* const* d_in, const int* in_sizes, int n_in,
                              void* d_out, int out_size) {
    (void)in_sizes; (void)n_in; (void)out_size;
    const float* x = (const float*)d_in[0];
    const int* ei = (const int*)d_in[1];

    static cudaStream_t s_csr = nullptr;
    static cudaEvent_t ev_fork = nullptr, ev_join = nullptr;
    if (s_csr == nullptr) {
        cudaStreamCreateWithFlags(&s_csr, cudaStreamNonBlocking);
        cudaEventCreateWithFlags(&ev_fork, cudaEventDisableTiming);
        cudaEventCreateWithFlags(&ev_join, cudaEventDisableTiming);
        constexpr int SMEM1c = 8 * 4 * 32 * 16;
        constexpr int SMEM2c = 4 * 4 * 32 * 16;
        cudaFuncSetAttribute(gemm_mma_kernel<128, 1>,
                             cudaFuncAttributeMaxDynamicSharedMemorySize, SMEM1c);
        cudaFuncSetAttribute(gemm_mma_kernel<64, 2>,
                             cudaFuncAttributeMaxDynamicSharedMemorySize, SMEM2c);
    }
    constexpr int SMEM1 = 8 * 4 * 32 * 16;   // 16384 bytes (C=128)
    constexpr int SMEM2 = 4 * 4 * 32 * 16;   // 8192 bytes (C=64)

    G4w w1, w2;
    w1.W[0] = (const float*)d_in[2];  w1.b[0] = (const float*)d_in[3];
    w1.W[1] = (const float*)d_in[4];  w1.b[1] = (const float*)d_in[5];
    w1.W[2] = (const float*)d_in[6];  w1.b[2] = (const float*)d_in[7];
    w1.W[3] = (const float*)d_in[8];  w1.b[3] = (const float*)d_in[9];
    w2.W[0] = (const float*)d_in[10]; w2.b[0] = (const float*)d_in[11];
    w2.W[1] = (const float*)d_in[12]; w2.b[1] = (const float*)d_in[13];
    w2.W[2] = (const float*)d_in[14]; w2.b[2] = (const float*)d_in[15];
    w2.W[3] = (const float*)d_in[16]; w2.b[3] = (const float*)d_in[17];

    void* degp = nullptr;
    cudaGetSymbolAddress(&degp, g_deg);

    // ---- fork: CSR chain on side stream ----
    cudaEventRecord(ev_fork, 0);
    cudaStreamWaitEvent(s_csr, ev_fork, 0);
    cudaMemsetAsync(degp, 0, NN * sizeof(int), s_csr);
    hist_kernel<<<(EE + 255) / 256, 256, 0, s_csr>>>(ei);
    scan_kernel<<<1, 1024, 0, s_csr>>>();
    scatter_kernel<<<(EE + 255) / 256, 256, 0, s_csr>>>(ei);
    cudaEventRecord(ev_join, s_csr);

    // ---- main stream: wprep -> gemm1 (independent of CSR) ----
    wprep_kernel<<<48, 256>>>(w1, w2);
    const int NB = (NN + 63) / 64;   // 782
    gemm_mma_kernel<128, 1><<<NB, 256, SMEM1>>>(x, w1, 0.25f);   // qscale 1/4

    // ---- join, then the dependent chain (attn: 64-thread CTAs, 2 nodes) ----
    cudaStreamWaitEvent(0, ev_join, 0);
    node_attn_kernel<4, true, true><<<(NN * 32 + 63) / 64, 64>>>(nullptr);
    gemm_mma_kernel<64, 2><<<NB, 256, SMEM2>>>(x, w2, 0.125f);   // qscale 1/8
    node_attn_kernel<1, false, false><<<(NN * 32 + 63) / 64, 64>>>((float*)d_out);
}